// round 1
// baseline (speedup 1.0000x reference)
#include <cuda_runtime.h>
#include <math.h>

#define DIM 1024
#define NSK 50
#define MAXM 4096
#define KBIG (NSK * DIM)   // 51200

// Scratch: Hg[n][e*DIM+h] = gates[n,e] * relu(x[n] @ W1[e] + b1[e])[h]
__device__ float g_H[(size_t)MAXM * (size_t)KBIG];   // ~838 MB
__device__ float g_gates[(size_t)MAXM * NSK];

// ---------------------------------------------------------------------------
// Kernel 1: gating softmax + output bias-init
//   gates[n,e] = softmax_e(x[n] @ Wg + bg)
//   out[n,d]   = sum_e gates[n,e] * b2[e,d]     (initializes poisoned out)
// ---------------------------------------------------------------------------
__global__ __launch_bounds__(256) void gate_kernel(
    const float* __restrict__ x, const float* __restrict__ Wg,
    const float* __restrict__ bg, const float* __restrict__ b2,
    float* __restrict__ out)
{
    int n = blockIdx.x;
    __shared__ float xs[DIM];
    __shared__ float logit[NSK];
    __shared__ float gsm[NSK];

    int tid  = threadIdx.x;
    int warp = tid >> 5;
    int lane = tid & 31;

    for (int i = tid; i < DIM; i += 256) xs[i] = x[(size_t)n * DIM + i];
    __syncthreads();

    for (int e = warp; e < NSK; e += 8) {
        float s = 0.f;
        for (int d = lane; d < DIM; d += 32)
            s = fmaf(xs[d], Wg[(size_t)d * NSK + e], s);
        #pragma unroll
        for (int o = 16; o > 0; o >>= 1)
            s += __shfl_xor_sync(0xFFFFFFFFu, s, o);
        if (lane == 0) logit[e] = s + bg[e];
    }
    __syncthreads();

    if (tid == 0) {
        float mx = -1e30f;
        for (int e = 0; e < NSK; e++) mx = fmaxf(mx, logit[e]);
        float sum = 0.f;
        for (int e = 0; e < NSK; e++) {
            float v = expf(logit[e] - mx);
            gsm[e] = v;
            sum += v;
        }
        float inv = 1.f / sum;
        for (int e = 0; e < NSK; e++) gsm[e] *= inv;
    }
    __syncthreads();

    for (int e = tid; e < NSK; e += 256)
        g_gates[(size_t)n * NSK + e] = gsm[e];

    // out init = sum_e g[e] * b2[e, d]
    for (int d = tid; d < DIM; d += 256) {
        float acc = 0.f;
        #pragma unroll 10
        for (int e = 0; e < NSK; e++)
            acc = fmaf(gsm[e], b2[(size_t)e * DIM + d], acc);
        out[(size_t)n * DIM + d] = acc;
    }
}

// ---------------------------------------------------------------------------
// Kernel 2: batched GEMM1 over experts (grid.z = e)
//   Hg[m, e*DIM + n] = gates[m,e] * relu( sum_k X[m,k] * W1[e,k,n] + b1[e,n] )
// 128x128 tile, BK=8, 8x8 micro-tile, 256 threads.
// ---------------------------------------------------------------------------
__global__ __launch_bounds__(256) void gemm1_kernel(
    const float* __restrict__ X, const float* __restrict__ W1,
    const float* __restrict__ b1)
{
    const int K = DIM, N = DIM;
    int e = blockIdx.z;
    const float* B = W1 + (size_t)e * DIM * DIM;

    __shared__ float As[8][128];
    __shared__ float Bs[8][128];

    int tid = threadIdx.x;
    int m0 = blockIdx.y * 128;
    int n0 = blockIdx.x * 128;

    int a_row = tid >> 1;
    int a_col = (tid & 1) * 4;
    int b_row = tid >> 5;
    int b_col = (tid & 31) * 4;

    int ty = tid >> 4;   // 0..15 -> m micro-tile
    int tx = tid & 15;   // 0..15 -> n micro-tile

    float acc[8][8];
    #pragma unroll
    for (int i = 0; i < 8; i++)
        #pragma unroll
        for (int j = 0; j < 8; j++) acc[i][j] = 0.f;

    const float* Ap = X + (size_t)(m0 + a_row) * K + a_col;
    const float* Bp = B + (size_t)b_row * N + n0 + b_col;

    for (int k0 = 0; k0 < K; k0 += 8) {
        float4 av = *reinterpret_cast<const float4*>(Ap + k0);
        As[a_col + 0][a_row] = av.x;
        As[a_col + 1][a_row] = av.y;
        As[a_col + 2][a_row] = av.z;
        As[a_col + 3][a_row] = av.w;
        *reinterpret_cast<float4*>(&Bs[b_row][b_col]) =
            *reinterpret_cast<const float4*>(Bp + (size_t)k0 * N);
        __syncthreads();
        #pragma unroll
        for (int k = 0; k < 8; k++) {
            float4 a0 = *reinterpret_cast<const float4*>(&As[k][ty * 8]);
            float4 a1 = *reinterpret_cast<const float4*>(&As[k][ty * 8 + 4]);
            float4 c0 = *reinterpret_cast<const float4*>(&Bs[k][tx * 8]);
            float4 c1 = *reinterpret_cast<const float4*>(&Bs[k][tx * 8 + 4]);
            float ar[8] = {a0.x, a0.y, a0.z, a0.w, a1.x, a1.y, a1.z, a1.w};
            float br[8] = {c0.x, c0.y, c0.z, c0.w, c1.x, c1.y, c1.z, c1.w};
            #pragma unroll
            for (int i = 0; i < 8; i++)
                #pragma unroll
                for (int j = 0; j < 8; j++)
                    acc[i][j] = fmaf(ar[i], br[j], acc[i][j]);
        }
        __syncthreads();
    }

    // epilogue: +bias, relu, *gate, store to Hg
    float bv[8];
    #pragma unroll
    for (int j = 0; j < 8; j++)
        bv[j] = b1[(size_t)e * DIM + n0 + tx * 8 + j];

    #pragma unroll
    for (int i = 0; i < 8; i++) {
        int m = m0 + ty * 8 + i;
        float g = g_gates[(size_t)m * NSK + e];
        float* Hrow = g_H + (size_t)m * KBIG + (size_t)e * DIM + n0 + tx * 8;
        float4 v0, v1;
        float v[8];
        #pragma unroll
        for (int j = 0; j < 8; j++) {
            float t = acc[i][j] + bv[j];
            t = t > 0.f ? t : 0.f;
            v[j] = t * g;
        }
        v0.x = v[0]; v0.y = v[1]; v0.z = v[2]; v0.w = v[3];
        v1.x = v[4]; v1.y = v[5]; v1.z = v[6]; v1.w = v[7];
        *reinterpret_cast<float4*>(Hrow)     = v0;
        *reinterpret_cast<float4*>(Hrow + 4) = v1;
    }
}

// ---------------------------------------------------------------------------
// Kernel 3: monolithic GEMM2 over the fused expert dimension
//   out[m,d] += sum_{k=0}^{51200} Hg[m,k] * W2flat[k,d]
// (out already holds the gate-weighted b2 term)
// ---------------------------------------------------------------------------
__global__ __launch_bounds__(256) void gemm2_kernel(
    const float* __restrict__ W2, float* __restrict__ out)
{
    const int K = KBIG, N = DIM;

    __shared__ float As[8][128];
    __shared__ float Bs[8][128];

    int tid = threadIdx.x;
    int m0 = blockIdx.y * 128;
    int n0 = blockIdx.x * 128;

    int a_row = tid >> 1;
    int a_col = (tid & 1) * 4;
    int b_row = tid >> 5;
    int b_col = (tid & 31) * 4;

    int ty = tid >> 4;
    int tx = tid & 15;

    float acc[8][8];
    #pragma unroll
    for (int i = 0; i < 8; i++)
        #pragma unroll
        for (int j = 0; j < 8; j++) acc[i][j] = 0.f;

    const float* Ap = g_H + (size_t)(m0 + a_row) * K + a_col;
    const float* Bp = W2 + (size_t)b_row * N + n0 + b_col;

    for (int k0 = 0; k0 < K; k0 += 8) {
        float4 av = *reinterpret_cast<const float4*>(Ap + k0);
        As[a_col + 0][a_row] = av.x;
        As[a_col + 1][a_row] = av.y;
        As[a_col + 2][a_row] = av.z;
        As[a_col + 3][a_row] = av.w;
        *reinterpret_cast<float4*>(&Bs[b_row][b_col]) =
            *reinterpret_cast<const float4*>(Bp + (size_t)k0 * N);
        __syncthreads();
        #pragma unroll
        for (int k = 0; k < 8; k++) {
            float4 a0 = *reinterpret_cast<const float4*>(&As[k][ty * 8]);
            float4 a1 = *reinterpret_cast<const float4*>(&As[k][ty * 8 + 4]);
            float4 c0 = *reinterpret_cast<const float4*>(&Bs[k][tx * 8]);
            float4 c1 = *reinterpret_cast<const float4*>(&Bs[k][tx * 8 + 4]);
            float ar[8] = {a0.x, a0.y, a0.z, a0.w, a1.x, a1.y, a1.z, a1.w};
            float br[8] = {c0.x, c0.y, c0.z, c0.w, c1.x, c1.y, c1.z, c1.w};
            #pragma unroll
            for (int i = 0; i < 8; i++)
                #pragma unroll
                for (int j = 0; j < 8; j++)
                    acc[i][j] = fmaf(ar[i], br[j], acc[i][j]);
        }
        __syncthreads();
    }

    #pragma unroll
    for (int i = 0; i < 8; i++) {
        int m = m0 + ty * 8 + i;
        float* orow = out + (size_t)m * DIM + n0 + tx * 8;
        float4 o0 = *reinterpret_cast<const float4*>(orow);
        float4 o1 = *reinterpret_cast<const float4*>(orow + 4);
        o0.x += acc[i][0]; o0.y += acc[i][1]; o0.z += acc[i][2]; o0.w += acc[i][3];
        o1.x += acc[i][4]; o1.y += acc[i][5]; o1.z += acc[i][6]; o1.w += acc[i][7];
        *reinterpret_cast<float4*>(orow)     = o0;
        *reinterpret_cast<float4*>(orow + 4) = o1;
    }
}

// ---------------------------------------------------------------------------
extern "C" void kernel_launch(void* const* d_in, const int* in_sizes, int n_in,
                              void* d_out, int out_size)
{
    const float* x  = (const float*)d_in[0];
    const float* W1 = (const float*)d_in[1];
    const float* b1 = (const float*)d_in[2];
    const float* W2 = (const float*)d_in[3];
    const float* b2 = (const float*)d_in[4];
    const float* Wg = (const float*)d_in[5];
    const float* bg = (const float*)d_in[6];
    float* out = (float*)d_out;

    int M = in_sizes[0] / DIM;   // 4096

    gate_kernel<<<M, 256>>>(x, Wg, bg, b2, out);
    gemm1_kernel<<<dim3(DIM / 128, M / 128, NSK), 256>>>(x, W1, b1);
    gemm2_kernel<<<dim3(DIM / 128, M / 128), 256>>>(W2, out);
}

// round 2
// speedup vs baseline: 1.0011x; 1.0011x over previous
#include <cuda_runtime.h>
#include <math.h>

#define DIM 1024
#define NSK 50
#define MAXM 4096
#define KBIG (NSK * DIM)   // 51200

// Scratch: Hg[n][e*DIM+h] = gates[n,e] * relu(x[n] @ W1[e] + b1[e])[h]
__device__ float g_H[(size_t)MAXM * (size_t)KBIG];   // ~838 MB
__device__ float g_gates[(size_t)MAXM * NSK];

// ---------------------------------------------------------------------------
// Kernel 1: gating softmax + output bias-init
//   gates[n,e] = softmax_e(x[n] @ Wg + bg)
//   out[n,d]   = sum_e gates[n,e] * b2[e,d]     (initializes poisoned out)
// ---------------------------------------------------------------------------
__global__ __launch_bounds__(256) void gate_kernel(
    const float* __restrict__ x, const float* __restrict__ Wg,
    const float* __restrict__ bg, const float* __restrict__ b2,
    float* __restrict__ out)
{
    int n = blockIdx.x;
    __shared__ float xs[DIM];
    __shared__ float logit[NSK];
    __shared__ float gsm[NSK];

    int tid  = threadIdx.x;
    int warp = tid >> 5;
    int lane = tid & 31;

    for (int i = tid; i < DIM; i += 256) xs[i] = x[(size_t)n * DIM + i];
    __syncthreads();

    for (int e = warp; e < NSK; e += 8) {
        float s = 0.f;
        for (int d = lane; d < DIM; d += 32)
            s = fmaf(xs[d], Wg[(size_t)d * NSK + e], s);
        #pragma unroll
        for (int o = 16; o > 0; o >>= 1)
            s += __shfl_xor_sync(0xFFFFFFFFu, s, o);
        if (lane == 0) logit[e] = s + bg[e];
    }
    __syncthreads();

    if (tid == 0) {
        float mx = -1e30f;
        for (int e = 0; e < NSK; e++) mx = fmaxf(mx, logit[e]);
        float sum = 0.f;
        for (int e = 0; e < NSK; e++) {
            float v = expf(logit[e] - mx);
            gsm[e] = v;
            sum += v;
        }
        float inv = 1.f / sum;
        for (int e = 0; e < NSK; e++) gsm[e] *= inv;
    }
    __syncthreads();

    for (int e = tid; e < NSK; e += 256)
        g_gates[(size_t)n * NSK + e] = gsm[e];

    // out init = sum_e g[e] * b2[e, d]
    for (int d = tid; d < DIM; d += 256) {
        float acc = 0.f;
        #pragma unroll 10
        for (int e = 0; e < NSK; e++)
            acc = fmaf(gsm[e], b2[(size_t)e * DIM + d], acc);
        out[(size_t)n * DIM + d] = acc;
    }
}

// ---------------------------------------------------------------------------
// Kernel 2: batched GEMM1 over experts (grid.z = e)
//   Hg[m, e*DIM + n] = gates[m,e] * relu( sum_k X[m,k] * W1[e,k,n] + b1[e,n] )
// 128x128 tile, BK=8, 8x8 micro-tile, 256 threads.
// ---------------------------------------------------------------------------
__global__ __launch_bounds__(256) void gemm1_kernel(
    const float* __restrict__ X, const float* __restrict__ W1,
    const float* __restrict__ b1)
{
    const int K = DIM, N = DIM;
    int e = blockIdx.z;
    const float* B = W1 + (size_t)e * DIM * DIM;

    __shared__ float As[8][128];
    __shared__ float Bs[8][128];

    int tid = threadIdx.x;
    int m0 = blockIdx.y * 128;
    int n0 = blockIdx.x * 128;

    int a_row = tid >> 1;
    int a_col = (tid & 1) * 4;
    int b_row = tid >> 5;
    int b_col = (tid & 31) * 4;

    int ty = tid >> 4;   // 0..15 -> m micro-tile
    int tx = tid & 15;   // 0..15 -> n micro-tile

    float acc[8][8];
    #pragma unroll
    for (int i = 0; i < 8; i++)
        #pragma unroll
        for (int j = 0; j < 8; j++) acc[i][j] = 0.f;

    const float* Ap = X + (size_t)(m0 + a_row) * K + a_col;
    const float* Bp = B + (size_t)b_row * N + n0 + b_col;

    for (int k0 = 0; k0 < K; k0 += 8) {
        float4 av = *reinterpret_cast<const float4*>(Ap + k0);
        As[a_col + 0][a_row] = av.x;
        As[a_col + 1][a_row] = av.y;
        As[a_col + 2][a_row] = av.z;
        As[a_col + 3][a_row] = av.w;
        *reinterpret_cast<float4*>(&Bs[b_row][b_col]) =
            *reinterpret_cast<const float4*>(Bp + (size_t)k0 * N);
        __syncthreads();
        #pragma unroll
        for (int k = 0; k < 8; k++) {
            float4 a0 = *reinterpret_cast<const float4*>(&As[k][ty * 8]);
            float4 a1 = *reinterpret_cast<const float4*>(&As[k][ty * 8 + 4]);
            float4 c0 = *reinterpret_cast<const float4*>(&Bs[k][tx * 8]);
            float4 c1 = *reinterpret_cast<const float4*>(&Bs[k][tx * 8 + 4]);
            float ar[8] = {a0.x, a0.y, a0.z, a0.w, a1.x, a1.y, a1.z, a1.w};
            float br[8] = {c0.x, c0.y, c0.z, c0.w, c1.x, c1.y, c1.z, c1.w};
            #pragma unroll
            for (int i = 0; i < 8; i++)
                #pragma unroll
                for (int j = 0; j < 8; j++)
                    acc[i][j] = fmaf(ar[i], br[j], acc[i][j]);
        }
        __syncthreads();
    }

    // epilogue: +bias, relu, *gate, store to Hg
    float bv[8];
    #pragma unroll
    for (int j = 0; j < 8; j++)
        bv[j] = b1[(size_t)e * DIM + n0 + tx * 8 + j];

    #pragma unroll
    for (int i = 0; i < 8; i++) {
        int m = m0 + ty * 8 + i;
        float g = g_gates[(size_t)m * NSK + e];
        float* Hrow = g_H + (size_t)m * KBIG + (size_t)e * DIM + n0 + tx * 8;
        float4 v0, v1;
        float v[8];
        #pragma unroll
        for (int j = 0; j < 8; j++) {
            float t = acc[i][j] + bv[j];
            t = t > 0.f ? t : 0.f;
            v[j] = t * g;
        }
        v0.x = v[0]; v0.y = v[1]; v0.z = v[2]; v0.w = v[3];
        v1.x = v[4]; v1.y = v[5]; v1.z = v[6]; v1.w = v[7];
        *reinterpret_cast<float4*>(Hrow)     = v0;
        *reinterpret_cast<float4*>(Hrow + 4) = v1;
    }
}

// ---------------------------------------------------------------------------
// Kernel 3: monolithic GEMM2 over the fused expert dimension
//   out[m,d] += sum_{k=0}^{51200} Hg[m,k] * W2flat[k,d]
// (out already holds the gate-weighted b2 term)
// ---------------------------------------------------------------------------
__global__ __launch_bounds__(256) void gemm2_kernel(
    const float* __restrict__ W2, float* __restrict__ out)
{
    const int K = KBIG, N = DIM;

    __shared__ float As[8][128];
    __shared__ float Bs[8][128];

    int tid = threadIdx.x;
    int m0 = blockIdx.y * 128;
    int n0 = blockIdx.x * 128;

    int a_row = tid >> 1;
    int a_col = (tid & 1) * 4;
    int b_row = tid >> 5;
    int b_col = (tid & 31) * 4;

    int ty = tid >> 4;
    int tx = tid & 15;

    float acc[8][8];
    #pragma unroll
    for (int i = 0; i < 8; i++)
        #pragma unroll
        for (int j = 0; j < 8; j++) acc[i][j] = 0.f;

    const float* Ap = g_H + (size_t)(m0 + a_row) * K + a_col;
    const float* Bp = W2 + (size_t)b_row * N + n0 + b_col;

    for (int k0 = 0; k0 < K; k0 += 8) {
        float4 av = *reinterpret_cast<const float4*>(Ap + k0);
        As[a_col + 0][a_row] = av.x;
        As[a_col + 1][a_row] = av.y;
        As[a_col + 2][a_row] = av.z;
        As[a_col + 3][a_row] = av.w;
        *reinterpret_cast<float4*>(&Bs[b_row][b_col]) =
            *reinterpret_cast<const float4*>(Bp + (size_t)k0 * N);
        __syncthreads();
        #pragma unroll
        for (int k = 0; k < 8; k++) {
            float4 a0 = *reinterpret_cast<const float4*>(&As[k][ty * 8]);
            float4 a1 = *reinterpret_cast<const float4*>(&As[k][ty * 8 + 4]);
            float4 c0 = *reinterpret_cast<const float4*>(&Bs[k][tx * 8]);
            float4 c1 = *reinterpret_cast<const float4*>(&Bs[k][tx * 8 + 4]);
            float ar[8] = {a0.x, a0.y, a0.z, a0.w, a1.x, a1.y, a1.z, a1.w};
            float br[8] = {c0.x, c0.y, c0.z, c0.w, c1.x, c1.y, c1.z, c1.w};
            #pragma unroll
            for (int i = 0; i < 8; i++)
                #pragma unroll
                for (int j = 0; j < 8; j++)
                    acc[i][j] = fmaf(ar[i], br[j], acc[i][j]);
        }
        __syncthreads();
    }

    #pragma unroll
    for (int i = 0; i < 8; i++) {
        int m = m0 + ty * 8 + i;
        float* orow = out + (size_t)m * DIM + n0 + tx * 8;
        float4 o0 = *reinterpret_cast<const float4*>(orow);
        float4 o1 = *reinterpret_cast<const float4*>(orow + 4);
        o0.x += acc[i][0]; o0.y += acc[i][1]; o0.z += acc[i][2]; o0.w += acc[i][3];
        o1.x += acc[i][4]; o1.y += acc[i][5]; o1.z += acc[i][6]; o1.w += acc[i][7];
        *reinterpret_cast<float4*>(orow)     = o0;
        *reinterpret_cast<float4*>(orow + 4) = o1;
    }
}

// ---------------------------------------------------------------------------
extern "C" void kernel_launch(void* const* d_in, const int* in_sizes, int n_in,
                              void* d_out, int out_size)
{
    const float* x  = (const float*)d_in[0];
    const float* W1 = (const float*)d_in[1];
    const float* b1 = (const float*)d_in[2];
    const float* W2 = (const float*)d_in[3];
    const float* b2 = (const float*)d_in[4];
    const float* Wg = (const float*)d_in[5];
    const float* bg = (const float*)d_in[6];
    float* out = (float*)d_out;

    int M = in_sizes[0] / DIM;   // 4096

    gate_kernel<<<M, 256>>>(x, Wg, bg, b2, out);
    gemm1_kernel<<<dim3(DIM / 128, M / 128, NSK), 256>>>(x, W1, b1);
    gemm2_kernel<<<dim3(DIM / 128, M / 128), 256>>>(W2, out);
}